// round 16
// baseline (speedup 1.0000x reference)
#include <cuda_runtime.h>
#include <cuda_bf16.h>

// Problem constants (match reference)
#define WPIX 512.0f
#define HPIX 512.0f
#define S_MIN (1.0f / 30.0f)
#define S_MAX (1.0f / 0.75f)
#define MU_BORDER 1.05f
#define PI_APPROX 3.1416f

#define MAX_N 512
#define MAX_B 65536
#define TILE_PX 16.0f
#define TILES_X 32
#define TILES_Y 32
#define NUM_TILES (TILES_X * TILES_Y)
#define PRE_BLOCKS 16
#define G_PER_BLOCK 32        // 512 / 16
#define CAP 256               // bucket capacity per tile (mean load = 32)
#define MASK_WORDS 16         // 512 bits per tile
#define TPB 4                 // tiles per splat block
#define SPLAT_BLOCKS (NUM_TILES / TPB)   // 256
#define SMEM_GAUSS_BYTES (MAX_N * 9 * 16)  // 73728

// ---- per-gaussian precomputed data ----
__device__ float4 g_ga[MAX_N];          // (gmx, gmy, Sx, Sy), centered px coords
__device__ float4 g_gb[MAX_N];          // (cos a, sin a, sigmoid(op), 0)
__device__ float4 g_sh[MAX_N * 7];      // repacked 27 SH coeffs + pad

// ---- tile -> gaussian candidacy bitmasks (atomicOr = order-independent) ----
__device__ unsigned g_mask[NUM_TILES * MASK_WORDS];  // .bss zero; splat re-zeroes

// ---- direct ray buckets ----
__device__ int    g_hist[NUM_TILES];    // .bss zero; re-zeroed by splat each call
__device__ float2 g_bxy[NUM_TILES * CAP];
__device__ int    g_bid[NUM_TILES * CAP];
// overflow (correctness fallback; empty for benchmark inputs)
__device__ int    g_ovf_cnt;
__device__ float2 g_ovf_xy[MAX_B];
__device__ int    g_ovf_id[MAX_B];

__device__ __forceinline__ int tile_of(float xr, float yr) {
    int tx = min(TILES_X - 1, max(0, (int)(xr * (1.0f / TILE_PX))));
    int ty = min(TILES_Y - 1, max(0, (int)(yr * (1.0f / TILE_PX))));
    return ty * TILES_X + tx;
}

// Branchless per-pair accumulate: w==0 exactly when d2>=25, and
// fmaf(0, r, sum) == sum bitwise -> identical to the branchy skip.
__device__ __forceinline__ void splat_accum_bl(
    float px, float py, float4 ga, float4 gb,
    float4 q0, float4 q1, float4 q2, float4 q3,
    float4 q4, float4 q5, float4 q6,
    float& sumR, float& sumG, float& sumB)
{
    float vx = px - ga.x;
    float vy = py - ga.y;
    float svx = vx * ga.z;
    float svy = vy * ga.w;
    float d2 = fmaf(svx, svx, svy * svy);

    float c = gb.x, sa = gb.y;
    float w = (d2 < 25.0f) ? __expf(-d2) * gb.z : 0.0f;

    float rvx = c * vx - sa * vy;
    float rvy = fmaf(sa, vx, c * vy);
    float rn = rsqrtf(fmaf(rvx, rvx, fmaf(rvy, rvy, 1e-20f)));
    float s1 = rvx * rn;   // sin(theta)
    float c1 = rvy * rn;   // cos(theta)
    float s2 = 2.0f * s1 * c1;
    float c2 = fmaf(c1, c1, -s1 * s1);
    float s3 = fmaf(s1, c2, c1 * s2);
    float c3 = fmaf(c1, c2, -s1 * s2);
    float s4 = 2.0f * s2 * c2;
    float c4 = fmaf(c2, c2, -s2 * s2);

    float aR = q0.x;
    aR = fmaf(s1, q0.w, aR); aR = fmaf(c1, q1.z, aR);
    aR = fmaf(s2, q2.y, aR); aR = fmaf(c2, q3.x, aR);
    aR = fmaf(s3, q3.w, aR); aR = fmaf(c3, q4.z, aR);
    aR = fmaf(s4, q5.y, aR); aR = fmaf(c4, q6.x, aR);
    float aG = q0.y;
    aG = fmaf(s1, q1.x, aG); aG = fmaf(c1, q1.w, aG);
    aG = fmaf(s2, q2.z, aG); aG = fmaf(c2, q3.y, aG);
    aG = fmaf(s3, q4.x, aG); aG = fmaf(c3, q4.w, aG);
    aG = fmaf(s4, q5.z, aG); aG = fmaf(c4, q6.y, aG);
    float aB = q0.z;
    aB = fmaf(s1, q1.y, aB); aB = fmaf(c1, q2.x, aB);
    aB = fmaf(s2, q2.w, aB); aB = fmaf(c2, q3.z, aB);
    aB = fmaf(s3, q4.y, aB); aB = fmaf(c3, q5.x, aB);
    aB = fmaf(s4, q5.w, aB); aB = fmaf(c4, q6.z, aB);

    float rR = __fdividef(1.0f, 1.0f + __expf(-aR));
    float rG = __fdividef(1.0f, 1.0f + __expf(-aG));
    float rB = __fdividef(1.0f, 1.0f + __expf(-aB));
    sumR = fmaf(w, rR, sumR);
    sumG = fmaf(w, rG, sumG);
    sumB = fmaf(w, rB, sumB);
}

// ============================================================================
// K1: blocks [0, binBlocks): ray binning -> direct bucket scatter (2 rays/thr)
//     blocks [binBlocks, binBlocks+PRE_BLOCKS): per-gaussian precompute +
//       bitmask scatter (atomicOr, order-independent -> deterministic)
// ============================================================================
__global__ __launch_bounds__(256)
void prep_kernel(const float* __restrict__ x,
                 const float* __restrict__ rgbsh,
                 const float* __restrict__ opacity,
                 const float* __restrict__ mu,
                 const float* __restrict__ scale,
                 const float* __restrict__ angle,
                 int B, int N, int binBlocks) {
    int bid = blockIdx.x;
    int tid = threadIdx.x;

    if (bid < binBlocks) {
        const float4* x4 = (const float4*)x;
        int f = bid * 256 + tid;            // float4 index = rays 2f, 2f+1
        if (2 * f < B) {
            float4 v = x4[f];
#pragma unroll
            for (int j = 0; j < 2; ++j) {
                int r = 2 * f + j;
                if (r < B) {
                    float xr = (j == 0) ? v.x : v.z;
                    float yr = (j == 0) ? v.y : v.w;
                    int t = tile_of(xr, yr);
                    int pos = atomicAdd(&g_hist[t], 1);
                    if (pos < CAP) {
                        g_bxy[t * CAP + pos] = make_float2(xr, yr);
                        g_bid[t * CAP + pos] = r;
                    } else {
                        int o = atomicAdd(&g_ovf_cnt, 1);
                        g_ovf_xy[o] = make_float2(xr, yr);
                        g_ovf_id[o] = r;
                    }
                }
            }
        }
    } else {
        int g0 = (bid - binBlocks) * G_PER_BLOCK;
        if (tid < G_PER_BLOCK) {
            int n = g0 + tid;
            if (n < N) {
                float gmx = tanhf(mu[2 * n + 0]) * (MU_BORDER * WPIX * 0.5f);
                float gmy = tanhf(mu[2 * n + 1]) * (MU_BORDER * HPIX * 0.5f);
                float sx = fminf(fmaxf(scale[2 * n + 0], 0.0f), 1.0f) * (S_MAX - S_MIN) + S_MIN;
                float sy = fminf(fmaxf(scale[2 * n + 1], 0.0f), 1.0f) * (S_MAX - S_MIN) + S_MIN;
                g_ga[n] = make_float4(gmx, gmy, sx, sy);

                float alpha = tanhf(angle[n]) * PI_APPROX;
                float c, s;
                sincosf(alpha, &s, &c);
                float op = 1.0f / (1.0f + expf(-opacity[n]));
                g_gb[n] = make_float4(c, s, op, 0.0f);

                // conservative bbox of valid ellipse, raw pixel coords
                float hx = __fdividef(5.0f, sx) + 0.05f;
                float hy = __fdividef(5.0f, sy) + 0.05f;
                float cx = gmx + WPIX * 0.5f;
                float cy = gmy + HPIX * 0.5f;
                float xmin = cx - hx, xmax = cx + hx;
                float ymin = cy - hy, ymax = cy + hy;

                // tile rect overlapping bbox (conservative)
                int tx0 = max(0, (int)ceilf(xmin * (1.0f / TILE_PX)) - 1);
                int tx1 = min(TILES_X - 1, (int)floorf(xmax * (1.0f / TILE_PX)));
                int ty0 = max(0, (int)ceilf(ymin * (1.0f / TILE_PX)) - 1);
                int ty1 = min(TILES_Y - 1, (int)floorf(ymax * (1.0f / TILE_PX)));

                unsigned bit = 1u << (n & 31);
                int word = n >> 5;
                for (int ty = ty0; ty <= ty1; ++ty)
                    for (int tx = tx0; tx <= tx1; ++tx)
                        atomicOr(&g_mask[(ty * TILES_X + tx) * MASK_WORDS + word], bit);
            }
        } else {
            // SH repack: 224 tasks = 32 gaussians x 7 slots
            int task = tid - G_PER_BLOCK;
            int sl = task / 7;
            int j = task - sl * 7;
            int n = g0 + sl;
            if (n < N) {
                int c0 = 4 * j;
                float v0 = rgbsh[n * 27 + c0];
                float v1 = (c0 + 1 < 27) ? rgbsh[n * 27 + c0 + 1] : 0.0f;
                float v2 = (c0 + 2 < 27) ? rgbsh[n * 27 + c0 + 2] : 0.0f;
                float v3 = (c0 + 3 < 27) ? rgbsh[n * 27 + c0 + 3] : 0.0f;
                g_sh[n * 7 + j] = make_float4(v0, v1, v2, v3);
            }
        }
    }
}

// ============================================================================
// K2: splat — 4 tiles per block, 128 threads. ALL gaussian data staged into
// dynamic smem (one MLP-parallel round); per-tile control data prefetched
// upfront; candidate loop reads smem only. Warp w owns gaussians 128w..128w+127.
// Block SPLAT_BLOCKS: overflow fallback (empty in practice).
// ============================================================================
extern __shared__ float4 s_dyn[];   // [0,512): ga  [512,1024): gb  [1024,4608): sh

__global__ __launch_bounds__(128)
void splat_kernel(float* __restrict__ out, int B, int N) {
    int bid = blockIdx.x;
    int tid = threadIdx.x;
    int warp = tid >> 5;
    int lane = tid & 31;

    if (bid == SPLAT_BLOCKS) {
        int nOvf = g_ovf_cnt;
        __syncthreads();
        if (tid == 0) g_ovf_cnt = 0;
        int cap = (nOvf < MAX_B) ? nOvf : MAX_B;
        for (int i = tid; i < cap; i += 128) {
            float2 xy = g_ovf_xy[i];
            int ray = g_ovf_id[i];
            float px = xy.x - (WPIX * 0.5f);
            float py = xy.y - (HPIX * 0.5f);
            float sumR = 0.0f, sumG = 0.0f, sumB = 0.0f;
            for (int n = 0; n < N; ++n) {
                const float4* sh = &g_sh[n * 7];
                splat_accum_bl(px, py, g_ga[n], g_gb[n],
                               sh[0], sh[1], sh[2], sh[3], sh[4], sh[5], sh[6],
                               sumR, sumG, sumB);
            }
            out[3 * ray + 0] = sumR;
            out[3 * ray + 1] = sumG;
            out[3 * ray + 2] = sumB;
        }
        return;
    }

    __shared__ float s_red[4][32][3];

    int t0 = bid * TPB;

    // ---- prologue: ALL control loads issued upfront (independent, 1 round) ----
    int4 hist4 = *(const int4*)&g_hist[t0];            // t0 % 4 == 0 -> aligned
    uint4 mw[TPB];
    float2 xy0[TPB];
    int id0[TPB];
#pragma unroll
    for (int tg = 0; tg < TPB; ++tg) {
        mw[tg] = ((const uint4*)g_mask)[(t0 + tg) * 4 + warp];
        xy0[tg] = g_bxy[(t0 + tg) * CAP + lane];
        id0[tg] = g_bid[(t0 + tg) * CAP + lane];
    }
    // zero for replay idempotence
    if (lane == 0) {
#pragma unroll
        for (int tg = 0; tg < TPB; ++tg)
            ((uint4*)g_mask)[(t0 + tg) * 4 + warp] = make_uint4(0, 0, 0, 0);
    }
    if (tid == 0) *(int4*)&g_hist[t0] = make_int4(0, 0, 0, 0);

    // ---- stage ALL gaussian data into smem (independent loads, full MLP) ----
    for (int i = tid; i < N; i += 128) {
        s_dyn[i] = g_ga[i];
        s_dyn[MAX_N + i] = g_gb[i];
    }
    for (int i = tid; i < N * 7; i += 128)
        s_dyn[2 * MAX_N + i] = g_sh[i];
    __syncthreads();

    const float4* s_ga = s_dyn;
    const float4* s_gb = s_dyn + MAX_N;
    const float4* s_sh = s_dyn + 2 * MAX_N;

#pragma unroll
    for (int tg = 0; tg < TPB; ++tg) {
        int t = t0 + tg;
        int hist = (tg == 0) ? hist4.x : (tg == 1) ? hist4.y : (tg == 2) ? hist4.z : hist4.w;
        int rayCount = (hist < CAP) ? hist : CAP;
        if (rayCount == 0) continue;       // block-uniform -> sync-safe

        int bbase = t * CAP;
        for (int r0 = 0; r0 < rayCount; r0 += 32) {
            int myIdx = r0 + lane;
            bool active = myIdx < rayCount;
            float2 xy;
            int ray;
            if (r0 == 0) { xy = xy0[tg]; ray = id0[tg]; }
            else {
                int ci = (myIdx < CAP) ? myIdx : (CAP - 1);
                xy = g_bxy[bbase + ci];
                ray = g_bid[bbase + ci];
            }
            float px = xy.x - (WPIX * 0.5f);
            float py = xy.y - (HPIX * 0.5f);
            float sumR = 0.0f, sumG = 0.0f, sumB = 0.0f;

#pragma unroll
            for (int k = 0; k < 4; ++k) {
                unsigned word = (k == 0) ? mw[tg].x : (k == 1) ? mw[tg].y
                              : (k == 2) ? mw[tg].z : mw[tg].w;
                int nb = (warp * 4 + k) * 32;
                while (word) {                   // warp-uniform bit walk
                    int b = __ffs(word) - 1;
                    word &= word - 1;
                    int n = nb + b;
                    const float4* shp = &s_sh[n * 7];
                    splat_accum_bl(px, py, s_ga[n], s_gb[n],
                                   shp[0], shp[1], shp[2], shp[3],
                                   shp[4], shp[5], shp[6],
                                   sumR, sumG, sumB);
                }
            }

            s_red[warp][lane][0] = sumR;
            s_red[warp][lane][1] = sumG;
            s_red[warp][lane][2] = sumB;
            __syncthreads();

            if (warp == 0 && active) {
                // fixed order: ((w0 + w1) + w2) + w3 -> deterministic
                float r = ((s_red[0][lane][0] + s_red[1][lane][0]) + s_red[2][lane][0]) + s_red[3][lane][0];
                float g = ((s_red[0][lane][1] + s_red[1][lane][1]) + s_red[2][lane][1]) + s_red[3][lane][1];
                float b = ((s_red[0][lane][2] + s_red[1][lane][2]) + s_red[2][lane][2]) + s_red[3][lane][2];
                out[3 * ray + 0] = r;
                out[3 * ray + 1] = g;
                out[3 * ray + 2] = b;
            }
            __syncthreads();   // protect s_red before next batch/tile
        }
    }
}

extern "C" void kernel_launch(void* const* d_in, const int* in_sizes, int n_in,
                              void* d_out, int out_size) {
    // metadata order: x, rgbsh, opacity, mu, scale, angle
    const float* x       = (const float*)d_in[0];
    const float* rgbsh   = (const float*)d_in[1];
    const float* opacity = (const float*)d_in[2];
    const float* mu      = (const float*)d_in[3];
    const float* scale   = (const float*)d_in[4];
    const float* angle   = (const float*)d_in[5];
    float* out = (float*)d_out;

    int B = in_sizes[0] / 2;
    int N = in_sizes[2];
    if (N > MAX_N) N = MAX_N;

    // allow 72KB dynamic smem (idempotent, host-side attribute set)
    cudaFuncSetAttribute(splat_kernel,
                         cudaFuncAttributeMaxDynamicSharedMemorySize,
                         SMEM_GAUSS_BYTES);

    // binning: 2 rays per thread (one float4), 512 rays per 256-thread block
    int binBlocks = (B + 511) / 512;
    prep_kernel<<<binBlocks + PRE_BLOCKS, 256>>>(x, rgbsh, opacity, mu, scale, angle, B, N, binBlocks);

    splat_kernel<<<SPLAT_BLOCKS + 1, 128, SMEM_GAUSS_BYTES>>>(out, B, N);
}

// round 17
// speedup vs baseline: 1.3426x; 1.3426x over previous
#include <cuda_runtime.h>
#include <cuda_bf16.h>

// Problem constants (match reference)
#define WPIX 512.0f
#define HPIX 512.0f
#define S_MIN (1.0f / 30.0f)
#define S_MAX (1.0f / 0.75f)
#define MU_BORDER 1.05f
#define PI_APPROX 3.1416f

#define MAX_N 512
#define MAX_B 65536
#define TILE_PX 16.0f
#define TILES_X 32
#define TILES_Y 32
#define NUM_TILES (TILES_X * TILES_Y)
#define PRE_BLOCKS 16
#define G_PER_BLOCK 32        // 512 / 16
#define CAP 256               // bucket capacity per tile (mean load = 32)
#define MASK_WORDS 16         // 512 bits per tile
#define TPB 2                 // tiles per splat block
#define SPLAT_BLOCKS (NUM_TILES / TPB)   // 512
#define NLMAX 64              // per-warp candidate list cap (soft)

// ---- per-gaussian precomputed data ----
__device__ float4 g_ga[MAX_N];          // (gmx, gmy, Sx, Sy), centered px coords
__device__ float4 g_gb[MAX_N];          // (cos a, sin a, sigmoid(op), 0)
__device__ float4 g_sh[MAX_N * 7];      // repacked 27 SH coeffs + pad

// ---- tile -> gaussian candidacy bitmasks (atomicOr = order-independent) ----
__device__ unsigned g_mask[NUM_TILES * MASK_WORDS];  // .bss zero; splat re-zeroes

// ---- direct ray buckets ----
__device__ int    g_hist[NUM_TILES];    // .bss zero; re-zeroed by splat each call
__device__ float2 g_bxy[NUM_TILES * CAP];
__device__ int    g_bid[NUM_TILES * CAP];
// overflow (correctness fallback; empty for benchmark inputs)
__device__ int    g_ovf_cnt;
__device__ float2 g_ovf_xy[MAX_B];
__device__ int    g_ovf_id[MAX_B];

__device__ __forceinline__ int tile_of(float xr, float yr) {
    int tx = min(TILES_X - 1, max(0, (int)(xr * (1.0f / TILE_PX))));
    int ty = min(TILES_Y - 1, max(0, (int)(yr * (1.0f / TILE_PX))));
    return ty * TILES_X + tx;
}

// Branchless per-pair accumulate: w==0 exactly when d2>=25, and
// fmaf(0, r, sum) == sum bitwise -> identical to the branchy skip.
__device__ __forceinline__ void splat_accum_bl(
    float px, float py, float4 ga, float4 gb,
    float4 q0, float4 q1, float4 q2, float4 q3,
    float4 q4, float4 q5, float4 q6,
    float& sumR, float& sumG, float& sumB)
{
    float vx = px - ga.x;
    float vy = py - ga.y;
    float svx = vx * ga.z;
    float svy = vy * ga.w;
    float d2 = fmaf(svx, svx, svy * svy);

    float c = gb.x, sa = gb.y;
    float w = (d2 < 25.0f) ? __expf(-d2) * gb.z : 0.0f;

    float rvx = c * vx - sa * vy;
    float rvy = fmaf(sa, vx, c * vy);
    float rn = rsqrtf(fmaf(rvx, rvx, fmaf(rvy, rvy, 1e-20f)));
    float s1 = rvx * rn;   // sin(theta)
    float c1 = rvy * rn;   // cos(theta)
    float s2 = 2.0f * s1 * c1;
    float c2 = fmaf(c1, c1, -s1 * s1);
    float s3 = fmaf(s1, c2, c1 * s2);
    float c3 = fmaf(c1, c2, -s1 * s2);
    float s4 = 2.0f * s2 * c2;
    float c4 = fmaf(c2, c2, -s2 * s2);

    float aR = q0.x;
    aR = fmaf(s1, q0.w, aR); aR = fmaf(c1, q1.z, aR);
    aR = fmaf(s2, q2.y, aR); aR = fmaf(c2, q3.x, aR);
    aR = fmaf(s3, q3.w, aR); aR = fmaf(c3, q4.z, aR);
    aR = fmaf(s4, q5.y, aR); aR = fmaf(c4, q6.x, aR);
    float aG = q0.y;
    aG = fmaf(s1, q1.x, aG); aG = fmaf(c1, q1.w, aG);
    aG = fmaf(s2, q2.z, aG); aG = fmaf(c2, q3.y, aG);
    aG = fmaf(s3, q4.x, aG); aG = fmaf(c3, q4.w, aG);
    aG = fmaf(s4, q5.z, aG); aG = fmaf(c4, q6.y, aG);
    float aB = q0.z;
    aB = fmaf(s1, q1.y, aB); aB = fmaf(c1, q2.x, aB);
    aB = fmaf(s2, q2.w, aB); aB = fmaf(c2, q3.z, aB);
    aB = fmaf(s3, q4.y, aB); aB = fmaf(c3, q5.x, aB);
    aB = fmaf(s4, q5.w, aB); aB = fmaf(c4, q6.z, aB);

    float rR = __fdividef(1.0f, 1.0f + __expf(-aR));
    float rG = __fdividef(1.0f, 1.0f + __expf(-aG));
    float rB = __fdividef(1.0f, 1.0f + __expf(-aB));
    sumR = fmaf(w, rR, sumR);
    sumG = fmaf(w, rG, sumG);
    sumB = fmaf(w, rB, sumB);
}

// ============================================================================
// K1: blocks [0, binBlocks): ray binning -> direct bucket scatter (2 rays/thr)
//     blocks [binBlocks, binBlocks+PRE_BLOCKS): per-gaussian precompute +
//       bitmask scatter (atomicOr, order-independent -> deterministic)
// ============================================================================
__global__ __launch_bounds__(256)
void prep_kernel(const float* __restrict__ x,
                 const float* __restrict__ rgbsh,
                 const float* __restrict__ opacity,
                 const float* __restrict__ mu,
                 const float* __restrict__ scale,
                 const float* __restrict__ angle,
                 int B, int N, int binBlocks) {
    int bid = blockIdx.x;
    int tid = threadIdx.x;

    if (bid < binBlocks) {
        const float4* x4 = (const float4*)x;
        int f = bid * 256 + tid;            // float4 index = rays 2f, 2f+1
        if (2 * f < B) {
            float4 v = x4[f];
#pragma unroll
            for (int j = 0; j < 2; ++j) {
                int r = 2 * f + j;
                if (r < B) {
                    float xr = (j == 0) ? v.x : v.z;
                    float yr = (j == 0) ? v.y : v.w;
                    int t = tile_of(xr, yr);
                    int pos = atomicAdd(&g_hist[t], 1);
                    if (pos < CAP) {
                        g_bxy[t * CAP + pos] = make_float2(xr, yr);
                        g_bid[t * CAP + pos] = r;
                    } else {
                        int o = atomicAdd(&g_ovf_cnt, 1);
                        g_ovf_xy[o] = make_float2(xr, yr);
                        g_ovf_id[o] = r;
                    }
                }
            }
        }
    } else {
        int g0 = (bid - binBlocks) * G_PER_BLOCK;
        if (tid < G_PER_BLOCK) {
            int n = g0 + tid;
            if (n < N) {
                float gmx = tanhf(mu[2 * n + 0]) * (MU_BORDER * WPIX * 0.5f);
                float gmy = tanhf(mu[2 * n + 1]) * (MU_BORDER * HPIX * 0.5f);
                float sx = fminf(fmaxf(scale[2 * n + 0], 0.0f), 1.0f) * (S_MAX - S_MIN) + S_MIN;
                float sy = fminf(fmaxf(scale[2 * n + 1], 0.0f), 1.0f) * (S_MAX - S_MIN) + S_MIN;
                g_ga[n] = make_float4(gmx, gmy, sx, sy);

                float alpha = tanhf(angle[n]) * PI_APPROX;
                float c, s;
                sincosf(alpha, &s, &c);
                float op = 1.0f / (1.0f + expf(-opacity[n]));
                g_gb[n] = make_float4(c, s, op, 0.0f);

                // conservative bbox of valid ellipse, raw pixel coords
                float hx = __fdividef(5.0f, sx) + 0.05f;
                float hy = __fdividef(5.0f, sy) + 0.05f;
                float cx = gmx + WPIX * 0.5f;
                float cy = gmy + HPIX * 0.5f;
                float xmin = cx - hx, xmax = cx + hx;
                float ymin = cy - hy, ymax = cy + hy;

                // tile rect overlapping bbox (conservative)
                int tx0 = max(0, (int)ceilf(xmin * (1.0f / TILE_PX)) - 1);
                int tx1 = min(TILES_X - 1, (int)floorf(xmax * (1.0f / TILE_PX)));
                int ty0 = max(0, (int)ceilf(ymin * (1.0f / TILE_PX)) - 1);
                int ty1 = min(TILES_Y - 1, (int)floorf(ymax * (1.0f / TILE_PX)));

                unsigned bit = 1u << (n & 31);
                int word = n >> 5;
                for (int ty = ty0; ty <= ty1; ++ty)
                    for (int tx = tx0; tx <= tx1; ++tx)
                        atomicOr(&g_mask[(ty * TILES_X + tx) * MASK_WORDS + word], bit);
            }
        } else {
            // SH repack: 224 tasks = 32 gaussians x 7 slots
            int task = tid - G_PER_BLOCK;
            int sl = task / 7;
            int j = task - sl * 7;
            int n = g0 + sl;
            if (n < N) {
                int c0 = 4 * j;
                float v0 = rgbsh[n * 27 + c0];
                float v1 = (c0 + 1 < 27) ? rgbsh[n * 27 + c0 + 1] : 0.0f;
                float v2 = (c0 + 2 < 27) ? rgbsh[n * 27 + c0 + 2] : 0.0f;
                float v3 = (c0 + 3 < 27) ? rgbsh[n * 27 + c0 + 3] : 0.0f;
                g_sh[n * 7 + j] = make_float4(v0, v1, v2, v3);
            }
        }
    }
}

// ============================================================================
// K2: splat — 2 tiles per block, 128 threads; warp w owns gaussians
// 128w..128w+127 of each tile. Candidate indices collected in-registers
// (ALU only), then a 2-stage software pipeline issues candidate i+1's loads
// before candidate i's math. Fixed-order cross-warp reduce.
// Block SPLAT_BLOCKS: overflow fallback (empty in practice).
// ============================================================================
#define LOAD_CAND(n, ga, gb, q0, q1, q2, q3, q4, q5, q6) \
    do {                                                  \
        ga = g_ga[n];                                     \
        gb = g_gb[n];                                     \
        const float4* _shp = &g_sh[(n) * 7];              \
        q0 = _shp[0]; q1 = _shp[1]; q2 = _shp[2];         \
        q3 = _shp[3]; q4 = _shp[4]; q5 = _shp[5];         \
        q6 = _shp[6];                                     \
    } while (0)

__global__ __launch_bounds__(128)
void splat_kernel(float* __restrict__ out, int B, int N) {
    int bid = blockIdx.x;
    int tid = threadIdx.x;
    int warp = tid >> 5;
    int lane = tid & 31;

    if (bid == SPLAT_BLOCKS) {
        int nOvf = g_ovf_cnt;
        __syncthreads();
        if (tid == 0) g_ovf_cnt = 0;
        int cap = (nOvf < MAX_B) ? nOvf : MAX_B;
        for (int i = tid; i < cap; i += 128) {
            float2 xy = g_ovf_xy[i];
            int ray = g_ovf_id[i];
            float px = xy.x - (WPIX * 0.5f);
            float py = xy.y - (HPIX * 0.5f);
            float sumR = 0.0f, sumG = 0.0f, sumB = 0.0f;
            for (int n = 0; n < N; ++n) {
                const float4* sh = &g_sh[n * 7];
                splat_accum_bl(px, py, g_ga[n], g_gb[n],
                               sh[0], sh[1], sh[2], sh[3], sh[4], sh[5], sh[6],
                               sumR, sumG, sumB);
            }
            out[3 * ray + 0] = sumR;
            out[3 * ray + 1] = sumG;
            out[3 * ray + 2] = sumB;
        }
        return;
    }

    __shared__ float s_red[4][32][3];

    int t0 = bid * TPB;

    // ---- prologue: all control loads issued upfront (independent) ----
    int2 hist2 = *(const int2*)&g_hist[t0];            // t0 even -> 8B aligned
    uint4 mw[TPB];
    float2 xy0[TPB];
    int id0[TPB];
#pragma unroll
    for (int tg = 0; tg < TPB; ++tg) {
        mw[tg] = ((const uint4*)g_mask)[(t0 + tg) * 4 + warp];
        xy0[tg] = g_bxy[(t0 + tg) * CAP + lane];
        id0[tg] = g_bid[(t0 + tg) * CAP + lane];
    }
    // zero for replay idempotence
    if (lane == 0) {
#pragma unroll
        for (int tg = 0; tg < TPB; ++tg)
            ((uint4*)g_mask)[(t0 + tg) * 4 + warp] = make_uint4(0, 0, 0, 0);
    }
    if (tid == 0) *(int2*)&g_hist[t0] = make_int2(0, 0);

#pragma unroll
    for (int tg = 0; tg < TPB; ++tg) {
        int t = t0 + tg;
        int hist = (tg == 0) ? hist2.x : hist2.y;
        int rayCount = (hist < CAP) ? hist : CAP;
        if (rayCount == 0) continue;       // block-uniform -> sync-safe

        // ---- collect this warp's candidate indices (pure ALU, ascending) ----
        int nl[NLMAX];
        int wcnt = 0;
#pragma unroll
        for (int k = 0; k < 4; ++k) {
            unsigned word = (k == 0) ? mw[tg].x : (k == 1) ? mw[tg].y
                          : (k == 2) ? mw[tg].z : mw[tg].w;
            int nb = (warp * 4 + k) * 32;
            while (word) {
                int b = __ffs(word) - 1;
                word &= word - 1;
                if (wcnt < NLMAX) nl[wcnt] = nb + b;
                ++wcnt;
            }
        }
        int lcnt = (wcnt < NLMAX) ? wcnt : NLMAX;

        int bbase = t * CAP;
        for (int r0 = 0; r0 < rayCount; r0 += 32) {
            int myIdx = r0 + lane;
            bool active = myIdx < rayCount;
            float2 xy;
            int ray;
            if (r0 == 0) { xy = xy0[tg]; ray = id0[tg]; }
            else {
                int ci = (myIdx < CAP) ? myIdx : (CAP - 1);
                xy = g_bxy[bbase + ci];
                ray = g_bid[bbase + ci];
            }
            float px = xy.x - (WPIX * 0.5f);
            float py = xy.y - (HPIX * 0.5f);
            float sumR = 0.0f, sumG = 0.0f, sumB = 0.0f;

            // ---- 2-stage software pipeline over candidates ----
            if (lcnt > 0) {
                float4 cga, cgb, cq0, cq1, cq2, cq3, cq4, cq5, cq6;
                LOAD_CAND(nl[0], cga, cgb, cq0, cq1, cq2, cq3, cq4, cq5, cq6);
                for (int i = 0; i < lcnt; ++i) {
                    float4 nga, ngb, nq0, nq1, nq2, nq3, nq4, nq5, nq6;
                    int nn = (i + 1 < lcnt) ? nl[i + 1] : nl[i];
                    // next candidate's loads issue BEFORE current math
                    LOAD_CAND(nn, nga, ngb, nq0, nq1, nq2, nq3, nq4, nq5, nq6);
                    splat_accum_bl(px, py, cga, cgb, cq0, cq1, cq2, cq3,
                                   cq4, cq5, cq6, sumR, sumG, sumB);
                    cga = nga; cgb = ngb;
                    cq0 = nq0; cq1 = nq1; cq2 = nq2; cq3 = nq3;
                    cq4 = nq4; cq5 = nq5; cq6 = nq6;
                }
            }
            // soft-cap overflow (practically impossible): direct walk for rest
            if (wcnt > NLMAX) {
                int seen = 0;
#pragma unroll
                for (int k = 0; k < 4; ++k) {
                    unsigned word = (k == 0) ? mw[tg].x : (k == 1) ? mw[tg].y
                                  : (k == 2) ? mw[tg].z : mw[tg].w;
                    int nb = (warp * 4 + k) * 32;
                    while (word) {
                        int b = __ffs(word) - 1;
                        word &= word - 1;
                        if (seen >= NLMAX) {
                            int n = nb + b;
                            const float4* shp = &g_sh[n * 7];
                            splat_accum_bl(px, py, g_ga[n], g_gb[n],
                                           shp[0], shp[1], shp[2], shp[3],
                                           shp[4], shp[5], shp[6],
                                           sumR, sumG, sumB);
                        }
                        ++seen;
                    }
                }
            }

            s_red[warp][lane][0] = sumR;
            s_red[warp][lane][1] = sumG;
            s_red[warp][lane][2] = sumB;
            __syncthreads();

            if (warp == 0 && active) {
                // fixed order: ((w0 + w1) + w2) + w3 -> deterministic
                float r = ((s_red[0][lane][0] + s_red[1][lane][0]) + s_red[2][lane][0]) + s_red[3][lane][0];
                float g = ((s_red[0][lane][1] + s_red[1][lane][1]) + s_red[2][lane][1]) + s_red[3][lane][1];
                float b = ((s_red[0][lane][2] + s_red[1][lane][2]) + s_red[2][lane][2]) + s_red[3][lane][2];
                out[3 * ray + 0] = r;
                out[3 * ray + 1] = g;
                out[3 * ray + 2] = b;
            }
            __syncthreads();   // protect s_red before next batch/tile
        }
    }
}

extern "C" void kernel_launch(void* const* d_in, const int* in_sizes, int n_in,
                              void* d_out, int out_size) {
    // metadata order: x, rgbsh, opacity, mu, scale, angle
    const float* x       = (const float*)d_in[0];
    const float* rgbsh   = (const float*)d_in[1];
    const float* opacity = (const float*)d_in[2];
    const float* mu      = (const float*)d_in[3];
    const float* scale   = (const float*)d_in[4];
    const float* angle   = (const float*)d_in[5];
    float* out = (float*)d_out;

    int B = in_sizes[0] / 2;
    int N = in_sizes[2];
    if (N > MAX_N) N = MAX_N;

    // binning: 2 rays per thread (one float4), 512 rays per 256-thread block
    int binBlocks = (B + 511) / 512;
    prep_kernel<<<binBlocks + PRE_BLOCKS, 256>>>(x, rgbsh, opacity, mu, scale, angle, B, N, binBlocks);

    splat_kernel<<<SPLAT_BLOCKS + 1, 128>>>(out, B, N);
}